// round 1
// baseline (speedup 1.0000x reference)
#include <cuda_runtime.h>
#include <math.h>

#define LQ      1024
#define BATCH   2
#define DMODEL  1024
#define NH      16
#define DHD     64
#define MEMLEN  1024
#define TT      2048            // T = L + M
#define NG      (BATCH*NH)      // 32 batched heads
#define SCALE_F 0.125f          // 1/sqrt(64)
#define NEGBIG  -1e30f

// ---------------- scratch (device globals; no allocation allowed) -------------
__device__ float g_q [NG*LQ*DHD];                    //  8 MB  [b][h][i][d]
__device__ float g_k [NG*TT*DHD];                    // 16 MB  [b][h][t][d]
__device__ float g_v [NG*TT*DHD];                    // 16 MB
__device__ float g_r [NG*TT*DHD];                    // 16 MB
__device__ float g_s [(size_t)NG*LQ*TT];             // 256 MB scores -> probs
__device__ float g_bd[(size_t)NG*LQ*TT];             // 256 MB BD (pre-shift)
__device__ float g_av[LQ*BATCH*NH*DHD];              //  8 MB  [(i*B+b)][h*64+d]
__device__ float g_h [LQ*BATCH*DMODEL];              //  8 MB  pre-LN residual

// ---------------- reductions ----------------
__device__ __forceinline__ float warpSum(float v){
    #pragma unroll
    for (int o=16;o>0;o>>=1) v += __shfl_xor_sync(0xffffffffu, v, o);
    return v;
}
__device__ __forceinline__ float blockSum(float v){
    __shared__ float sm[32];
    int lane = threadIdx.x & 31, w = threadIdx.x >> 5;
    v = warpSum(v);
    if (lane==0) sm[w] = v;
    __syncthreads();
    float r = (threadIdx.x < 8) ? sm[threadIdx.x] : 0.f;
    if (w==0){
        #pragma unroll
        for (int o=4;o>0;o>>=1) r += __shfl_xor_sync(0xffffffffu, r, o);
        if (lane==0) sm[0]=r;
    }
    __syncthreads();
    r = sm[0];
    __syncthreads();
    return r;
}
__device__ __forceinline__ float blockMax(float v){
    __shared__ float sm[32];
    int lane = threadIdx.x & 31, w = threadIdx.x >> 5;
    #pragma unroll
    for (int o=16;o>0;o>>=1) v = fmaxf(v, __shfl_xor_sync(0xffffffffu, v, o));
    if (lane==0) sm[w] = v;
    __syncthreads();
    float r = (threadIdx.x < 8) ? sm[threadIdx.x] : -3.4e38f;
    if (w==0){
        #pragma unroll
        for (int o=4;o>0;o>>=1) r = fmaxf(r, __shfl_xor_sync(0xffffffffu, r, o));
        if (lane==0) sm[0]=r;
    }
    __syncthreads();
    r = sm[0];
    __syncthreads();
    return r;
}

// ---------------- projection GEMM: C[rows, N] = A[rows,1024] @ W[1024,N] ------
// MODE 0: A=x (row=i*B+b), N=1024 -> g_q[b][h][i][d]
// MODE 1: A=concat(memory,x) (row=t*B+b), N=2048 -> g_k / g_v
// MODE 2: A=pos_emb, N=1024 -> g_r
// MODE 3: A=g_av (row=i*B+b), W=Wo, N=1024 -> g_h = x + A@Wo
template<int MODE, int N>
__global__ __launch_bounds__(256) void proj_gemm(const float* __restrict__ A0,
                                                 const float* __restrict__ A1,
                                                 const float* __restrict__ W)
{
    constexpr int BM=128, BN=128, BK=8;
    const int m0 = blockIdx.y * BM;
    const int n0 = blockIdx.x * BN;
    __shared__ float As[BK][BM];
    __shared__ float Ws[BK][BN];
    const int tid = threadIdx.x;
    const int a_r = tid >> 1;            // 0..127
    const int a_c = (tid & 1) * 4;       // 0 / 4
    const int w_r = tid >> 5;            // 0..7
    const int w_c = (tid & 31) * 4;
    const int tx = tid & 15, ty = tid >> 4;

    float acc[8][8];
    #pragma unroll
    for (int m=0;m<8;m++)
        #pragma unroll
        for (int n=0;n<8;n++) acc[m][n]=0.f;

    const int grow = m0 + a_r;
    const float* arow;
    if (MODE==1) arow = (grow < MEMLEN*BATCH) ? (A0 + (size_t)grow*DMODEL)
                                              : (A1 + (size_t)(grow - MEMLEN*BATCH)*DMODEL);
    else if (MODE==3) arow = g_av + (size_t)grow*DMODEL;
    else              arow = A0 + (size_t)grow*DMODEL;

    for (int k0=0;k0<DMODEL;k0+=BK){
        float4 av = *(const float4*)(arow + k0 + a_c);
        As[a_c+0][a_r]=av.x; As[a_c+1][a_r]=av.y; As[a_c+2][a_r]=av.z; As[a_c+3][a_r]=av.w;
        float4 wv = *(const float4*)(W + (size_t)(k0+w_r)*N + n0 + w_c);
        *(float4*)&Ws[w_r][w_c] = wv;
        __syncthreads();
        #pragma unroll
        for (int kk=0;kk<BK;kk++){
            float4 a0v = *(const float4*)&As[kk][ty*8];
            float4 a1v = *(const float4*)&As[kk][ty*8+4];
            float4 b0v = *(const float4*)&Ws[kk][tx*8];
            float4 b1v = *(const float4*)&Ws[kk][tx*8+4];
            float a[8] = {a0v.x,a0v.y,a0v.z,a0v.w,a1v.x,a1v.y,a1v.z,a1v.w};
            float b[8] = {b0v.x,b0v.y,b0v.z,b0v.w,b1v.x,b1v.y,b1v.z,b1v.w};
            #pragma unroll
            for (int m=0;m<8;m++)
                #pragma unroll
                for (int n=0;n<8;n++)
                    acc[m][n] = fmaf(a[m], b[n], acc[m][n]);
        }
        __syncthreads();
    }

    #pragma unroll
    for (int m=0;m<8;m++){
        const int row = m0 + ty*8 + m;
        #pragma unroll
        for (int n=0;n<8;n++){
            const int col = n0 + tx*8 + n;
            const float val = acc[m][n];
            if (MODE==0){
                int i = row / BATCH, b = row % BATCH;
                int h = col >> 6, d = col & 63;
                g_q[(((size_t)(b*NH+h)*LQ + i)<<6) + d] = val;
            } else if (MODE==1){
                int t = row / BATCH, b = row % BATCH;
                int c = col; float* dst = g_k;
                if (c >= NH*DHD){ dst = g_v; c -= NH*DHD; }
                int h = c >> 6, d = c & 63;
                dst[(((size_t)(b*NH+h)*TT + t)<<6) + d] = val;
            } else if (MODE==2){
                int t = row / BATCH, b = row % BATCH;
                int h = col >> 6, d = col & 63;
                g_r[(((size_t)(b*NH+h)*TT + t)<<6) + d] = val;
            } else {
                g_h[(size_t)row*DMODEL + col] = val + A1[(size_t)row*DMODEL + col];
            }
        }
    }
}

// ---------------- batched scores GEMM: S[g,i,j] = (q[g,i]+bias[h]) . K[g,j] ---
// WHICH 0: K=g_k -> g_s (AC term);  WHICH 1: K=g_r -> g_bd (BD term, pre-shift)
template<int WHICH>
__global__ __launch_bounds__(256) void scores_gemm(const float* __restrict__ bias)
{
    const float* Kk = WHICH ? g_r : g_k;
    float*       S  = WHICH ? g_bd : g_s;
    const int g  = blockIdx.z;
    const int h  = g % NH;
    const int i0 = blockIdx.y * 64;
    const int j0 = blockIdx.x * 64;
    __shared__ float Qs[64][65];
    __shared__ float Ks[64][65];
    const int tid = threadIdx.x;
    {
        const int r  = tid >> 2;
        const int c0 = (tid & 3) * 16;
        const float* qp = g_q + (((size_t)g*LQ + i0 + r) << 6) + c0;
        const float* bp = bias + (h << 6) + c0;
        const float* kp = Kk + (((size_t)g*TT + j0 + r) << 6) + c0;
        #pragma unroll
        for (int q4=0;q4<4;q4++){
            float4 qv = *(const float4*)(qp + q4*4);
            float4 bv = *(const float4*)(bp + q4*4);
            Qs[r][c0+q4*4+0]=qv.x+bv.x; Qs[r][c0+q4*4+1]=qv.y+bv.y;
            Qs[r][c0+q4*4+2]=qv.z+bv.z; Qs[r][c0+q4*4+3]=qv.w+bv.w;
            float4 kv = *(const float4*)(kp + q4*4);
            Ks[r][c0+q4*4+0]=kv.x; Ks[r][c0+q4*4+1]=kv.y;
            Ks[r][c0+q4*4+2]=kv.z; Ks[r][c0+q4*4+3]=kv.w;
        }
    }
    __syncthreads();
    const int tx = tid & 15, ty = tid >> 4;
    float acc[4][4];
    #pragma unroll
    for (int m=0;m<4;m++)
        #pragma unroll
        for (int n=0;n<4;n++) acc[m][n]=0.f;
    #pragma unroll
    for (int d=0; d<64; d++){
        float a[4], b[4];
        #pragma unroll
        for (int m=0;m<4;m++) a[m]=Qs[ty*4+m][d];
        #pragma unroll
        for (int n=0;n<4;n++) b[n]=Ks[tx*4+n][d];
        #pragma unroll
        for (int m=0;m<4;m++)
            #pragma unroll
            for (int n=0;n<4;n++)
                acc[m][n] = fmaf(a[m], b[n], acc[m][n]);
    }
    #pragma unroll
    for (int m=0;m<4;m++){
        float* srow = S + ((size_t)g*LQ + i0 + ty*4 + m)*TT + j0 + tx*4;
        #pragma unroll
        for (int n=0;n<4;n++) srow[n] = acc[m][n];
    }
}

// ---------------- softmax: in-place over g_s rows, reading shifted BD --------
__global__ __launch_bounds__(256) void softmax_kernel()
{
    const int idx = blockIdx.x;            // g*L + i
    const int i   = idx & (LQ-1);
    float* srow = g_s + (size_t)idx*TT;
    const float* bdrow = g_bd + (size_t)idx*TT;
    const int jmax = i + MEMLEN;
    const int tid = threadIdx.x;
    float vals[8];
    float mx = -3.4e38f;
    #pragma unroll
    for (int q=0;q<8;q++){
        int j = q*256 + tid;
        if (j <= jmax){
            float vv = (srow[j] + bdrow[j - i + LQ - 1]) * SCALE_F;
            vals[q] = vv;
            mx = fmaxf(mx, vv);
        } else vals[q] = NEGBIG;
    }
    mx = blockMax(mx);
    float s = 0.f;
    #pragma unroll
    for (int q=0;q<8;q++){
        float e = (vals[q] > -1e29f) ? __expf(vals[q]-mx) : 0.f;
        vals[q] = e; s += e;
    }
    s = blockSum(s);
    const float inv = 1.f / s;
    #pragma unroll
    for (int q=0;q<8;q++) srow[q*256 + tid] = vals[q] * inv;
}

// ---------------- attn_matrix = mean over (b,h) of probs ---------------------
__global__ __launch_bounds__(256) void attnmat_kernel(float* __restrict__ out)
{
    const size_t idx = (size_t)blockIdx.x*256 + threadIdx.x;   // over L*T
    float s = 0.f;
    #pragma unroll
    for (int g=0; g<NG; g++) s += g_s[(size_t)g*LQ*TT + idx];
    out[idx] = s * (1.f/NG);
}

// ---------------- PV: av[g,i,:] = P[g,i,:] @ V[g,:,:] ------------------------
__global__ __launch_bounds__(256) void pv_gemm()
{
    const int g  = blockIdx.y;
    const int i0 = blockIdx.x * 128;
    const int b  = g / NH, h = g % NH;
    __shared__ float Ps[32][132];
    __shared__ float Vs[32][68];
    const int tid = threadIdx.x;
    const int tx = tid & 15, ty = tid >> 4;
    float acc[8][4];
    #pragma unroll
    for (int m=0;m<8;m++)
        #pragma unroll
        for (int n=0;n<4;n++) acc[m][n]=0.f;
    const float* prow  = g_s + ((size_t)g*LQ + i0)*TT;
    const float* vbase = g_v + (((size_t)g*TT) << 6);
    for (int k0=0;k0<TT;k0+=32){
        {
            const int r  = tid >> 3;          // 0..31
            const int c0 = (tid & 7)*4;       // 0..28
            #pragma unroll
            for (int rr=0;rr<4;rr++){
                const int row = r + rr*32;
                float4 pv = *(const float4*)(prow + (size_t)row*TT + k0 + c0);
                Ps[c0+0][row]=pv.x; Ps[c0+1][row]=pv.y; Ps[c0+2][row]=pv.z; Ps[c0+3][row]=pv.w;
            }
            const int vr  = tid >> 4;         // 0..15
            const int vc0 = (tid & 15)*4;
            #pragma unroll
            for (int rr=0;rr<2;rr++){
                float4 vv = *(const float4*)(vbase + (size_t)(k0+vr+rr*16)*DHD + vc0);
                *(float4*)&Vs[vr+rr*16][vc0] = vv;
            }
        }
        __syncthreads();
        #pragma unroll
        for (int kk=0;kk<32;kk++){
            float a[8], bb[4];
            #pragma unroll
            for (int m=0;m<8;m++) a[m]=Ps[kk][ty*8+m];
            #pragma unroll
            for (int n=0;n<4;n++) bb[n]=Vs[kk][tx*4+n];
            #pragma unroll
            for (int m=0;m<8;m++)
                #pragma unroll
                for (int n=0;n<4;n++)
                    acc[m][n] = fmaf(a[m], bb[n], acc[m][n]);
        }
        __syncthreads();
    }
    #pragma unroll
    for (int m=0;m<8;m++){
        const int i = i0 + ty*8 + m;
        float* dst = g_av + ((size_t)(i*BATCH + b))*DMODEL + (h<<6) + tx*4;
        #pragma unroll
        for (int n=0;n<4;n++) dst[n] = acc[m][n];
    }
}

// ---------------- layernorm over D, writes output ----------------------------
__global__ __launch_bounds__(256) void ln_kernel(const float* __restrict__ gamma,
                                                 const float* __restrict__ beta,
                                                 float* __restrict__ out)
{
    const int row = blockIdx.x;
    const float* hr = g_h + (size_t)row*DMODEL;
    const int c = threadIdx.x * 4;
    float4 v = *(const float4*)(hr + c);
    float s = v.x+v.y+v.z+v.w;
    s = blockSum(s);
    const float mu = s * (1.f/DMODEL);
    float dx = v.x-mu, dy = v.y-mu, dz = v.z-mu, dw = v.w-mu;
    float sq = dx*dx+dy*dy+dz*dz+dw*dw;
    sq = blockSum(sq);
    const float inv = rsqrtf(sq*(1.f/DMODEL) + 1e-5f);
    float4 gm = *(const float4*)(gamma + c);
    float4 bt = *(const float4*)(beta + c);
    float4 o;
    o.x = dx*inv*gm.x + bt.x;
    o.y = dy*inv*gm.y + bt.y;
    o.z = dz*inv*gm.z + bt.z;
    o.w = dw*inv*gm.w + bt.w;
    *(float4*)(out + (size_t)row*DMODEL + c) = o;
}

// ---------------- launch ------------------------------------------------------
extern "C" void kernel_launch(void* const* d_in, const int* in_sizes, int n_in,
                              void* d_out, int out_size)
{
    const float* x        = (const float*)d_in[0];
    const float* pos_emb  = (const float*)d_in[1];
    const float* memory   = (const float*)d_in[2];
    const float* ubias    = (const float*)d_in[3];
    const float* vbias    = (const float*)d_in[4];
    // d_in[5] = mask (recomputed analytically)
    const float* Wq       = (const float*)d_in[6];
    const float* Wkv      = (const float*)d_in[7];
    const float* Wrel     = (const float*)d_in[8];
    const float* Wo       = (const float*)d_in[9];
    const float* gamma    = (const float*)d_in[10];
    const float* beta     = (const float*)d_in[11];
    float* out    = (float*)d_out;                     // [L,B,D]
    float* out_am = out + (size_t)LQ*BATCH*DMODEL;     // [L,T]

    proj_gemm<0,1024><<<dim3( 8,16), 256>>>(x,      nullptr, Wq);
    proj_gemm<1,2048><<<dim3(16,32), 256>>>(memory, x,       Wkv);
    proj_gemm<2,1024><<<dim3( 8,32), 256>>>(pos_emb,nullptr, Wrel);

    scores_gemm<0><<<dim3(TT/64, LQ/64, NG), 256>>>(ubias);   // AC -> g_s
    scores_gemm<1><<<dim3(TT/64, LQ/64, NG), 256>>>(vbias);   // BD -> g_bd

    softmax_kernel<<<NG*LQ, 256>>>();
    attnmat_kernel<<<(LQ*TT)/256, 256>>>(out_am);

    pv_gemm<<<dim3(LQ/128, NG), 256>>>();

    proj_gemm<3,1024><<<dim3(8,16), 256>>>(nullptr, x, Wo);   // g_h = x + av@Wo
    ln_kernel<<<LQ*BATCH, 256>>>(gamma, beta, out);
}